// round 6
// baseline (speedup 1.0000x reference)
#include <cuda_runtime.h>
#include <cuda_bf16.h>
#include <cstdint>

// ---------------------------------------------------------------------------
// BitNet-style MLP via exact int8 tensor-core GEMMs (IMMA m16n8k32.s8.s8.s32).
//   activation codes q in [-128,127], ternary weights t in {-1,0,1} -> int8.
//   s32 accumulation is exact; scales applied in fp32 epilogue.
// (tcgen05 is unavailable: harness PTX target is compute_103 without the 'a'
//  arch-feature suffix, so only the legacy mma.sync path exists.)
// ---------------------------------------------------------------------------

constexpr int MTOK = 8192;   // 4 * 2048 tokens
constexpr int DIM  = 1024;
constexpr int HID  = 4096;
constexpr int WNEL = HID * DIM;

// ------------------------- device scratch ----------------------------------
__device__ __align__(16) int8_t g_xq[MTOK * DIM];                   //  8 MB
__device__ __align__(16) int8_t g_hq[(size_t)MTOK * HID];           // 32 MB
__device__ __align__(16) int8_t g_w1q[WNEL];                        //  4 MB
__device__ __align__(16) int8_t g_w2q[WNEL];                        //  4 MB
__device__ __align__(16) float  g_h[(size_t)MTOK * HID];            // 128 MB
__device__ float g_xs[MTOK];
__device__ float g_hs[MTOK];
__device__ float g_part[2][1024];
__device__ float g_scales[4];   // s1, 1/s1, s2, 1/s2

// ------------------------- reductions --------------------------------------
__device__ __forceinline__ float warpSum(float v) {
#pragma unroll
    for (int o = 16; o > 0; o >>= 1) v += __shfl_xor_sync(0xffffffffu, v, o);
    return v;
}
__device__ __forceinline__ float warpMax(float v) {
#pragma unroll
    for (int o = 16; o > 0; o >>= 1) v = fmaxf(v, __shfl_xor_sync(0xffffffffu, v, o));
    return v;
}
__device__ float blockSum(float v) {
    __shared__ float sh[8];
    v = warpSum(v);
    if ((threadIdx.x & 31) == 0) sh[threadIdx.x >> 5] = v;
    __syncthreads();
    if (threadIdx.x == 0) {
        float t = sh[0];
#pragma unroll
        for (int i = 1; i < 8; i++) t += sh[i];
        sh[0] = t;
    }
    __syncthreads();
    float r = sh[0];
    __syncthreads();
    return r;
}
__device__ float blockMax(float v) {
    __shared__ float sh[8];
    v = warpMax(v);
    if ((threadIdx.x & 31) == 0) sh[threadIdx.x >> 5] = v;
    __syncthreads();
    if (threadIdx.x == 0) {
        float t = sh[0];
#pragma unroll
        for (int i = 1; i < 8; i++) t = fmaxf(t, sh[i]);
        sh[0] = t;
    }
    __syncthreads();
    float r = sh[0];
    __syncthreads();
    return r;
}

// ------------------------- weight quantization ------------------------------
__global__ void absmean_part(const float* __restrict__ w, int which) {
    float s = 0.f;
    for (int i = blockIdx.x * 256 + threadIdx.x; i < WNEL; i += 1024 * 256)
        s += fabsf(w[i]);
    s = blockSum(s);
    if (threadIdx.x == 0) g_part[which][blockIdx.x] = s;
}
__global__ void finalize_scales() {
    float s1 = 0.f, s2 = 0.f;
    for (int i = threadIdx.x; i < 1024; i += 256) { s1 += g_part[0][i]; s2 += g_part[1][i]; }
    s1 = blockSum(s1);
    s2 = blockSum(s2);
    if (threadIdx.x == 0) {
        float sc1 = __fdiv_rn(1.f, fmaxf(__fdiv_rn(s1, (float)WNEL), 1e-5f));
        float sc2 = __fdiv_rn(1.f, fmaxf(__fdiv_rn(s2, (float)WNEL), 1e-5f));
        g_scales[0] = sc1; g_scales[1] = __fdiv_rn(1.f, sc1);
        g_scales[2] = sc2; g_scales[3] = __fdiv_rn(1.f, sc2);
    }
}
// ternarize -> int8 codes. grid = WNEL/1024, block = 256, 4 elems/thread
__global__ void weight_quant_k(const float* __restrict__ w, int which) {
    int8_t* __restrict__ wq = which ? g_w2q : g_w1q;
    float s = g_scales[which * 2];
    size_t i = ((size_t)blockIdx.x * 256 + threadIdx.x) * 4;
    float4 v = *(const float4*)(w + i);
    int t0 = (int)fminf(fmaxf(rintf(v.x * s), -1.f), 1.f);
    int t1 = (int)fminf(fmaxf(rintf(v.y * s), -1.f), 1.f);
    int t2 = (int)fminf(fmaxf(rintf(v.z * s), -1.f), 1.f);
    int t3 = (int)fminf(fmaxf(rintf(v.w * s), -1.f), 1.f);
    uint32_t pk = (uint32_t)(t0 & 0xFF) | ((uint32_t)(t1 & 0xFF) << 8) |
                  ((uint32_t)(t2 & 0xFF) << 16) | ((uint32_t)(t3 & 0xFF) << 24);
    *(uint32_t*)(wq + i) = pk;
}

// ------------------------- rmsnorm + activation quant -----------------------
// One block (256 threads) per token. STAGE 0: x -> g_xq; STAGE 1: g_h -> g_hq.
template <int D, int STAGE>
__global__ void act_quant(const float* __restrict__ xin, const float* __restrict__ nw) {
    constexpr int E = D / 1024;
    const float* __restrict__ in = (STAGE == 0) ? xin : g_h;
    int8_t* __restrict__ xq = (STAGE == 0) ? g_xq : g_hq;
    float* __restrict__ xs = (STAGE == 0) ? g_xs : g_hs;
    size_t base = (size_t)blockIdx.x * D;

    float4 v[E], wv[E];
    float ss = 0.f;
#pragma unroll
    for (int e = 0; e < E; e++) {
        int idx = (e * 256 + threadIdx.x) * 4;
        v[e]  = *(const float4*)(in + base + idx);
        wv[e] = *(const float4*)(nw + idx);
        ss += v[e].x * v[e].x + v[e].y * v[e].y + v[e].z * v[e].z + v[e].w * v[e].w;
    }
    ss = blockSum(ss);
    float rsq = __fdiv_rn(1.f, __fsqrt_rn(__fdiv_rn(ss, (float)D) + 1e-8f));

    float mx = 0.f;
#pragma unroll
    for (int e = 0; e < E; e++) {
        v[e].x *= rsq * wv[e].x; v[e].y *= rsq * wv[e].y;
        v[e].z *= rsq * wv[e].z; v[e].w *= rsq * wv[e].w;
        mx = fmaxf(mx, fmaxf(fmaxf(fabsf(v[e].x), fabsf(v[e].y)),
                             fmaxf(fabsf(v[e].z), fabsf(v[e].w))));
    }
    mx = blockMax(mx);
    float sc = __fdiv_rn(127.f, fmaxf(mx, 1e-5f));

#pragma unroll
    for (int e = 0; e < E; e++) {
        int idx = (e * 256 + threadIdx.x) * 4;
        int q0 = (int)fminf(fmaxf(rintf(v[e].x * sc), -128.f), 127.f);
        int q1 = (int)fminf(fmaxf(rintf(v[e].y * sc), -128.f), 127.f);
        int q2 = (int)fminf(fmaxf(rintf(v[e].z * sc), -128.f), 127.f);
        int q3 = (int)fminf(fmaxf(rintf(v[e].w * sc), -128.f), 127.f);
        uint32_t pk = (uint32_t)(q0 & 0xFF) | ((uint32_t)(q1 & 0xFF) << 8) |
                      ((uint32_t)(q2 & 0xFF) << 16) | ((uint32_t)(q3 & 0xFF) << 24);
        *(uint32_t*)(xq + base + idx) = pk;
    }
    if (threadIdx.x == 0) xs[blockIdx.x] = __fdiv_rn(1.f, sc);
}

// ------------------------- int8 IMMA GEMM ----------------------------------
__device__ __forceinline__ void imma16832(int32_t* d, const uint32_t* a, const uint32_t* b) {
    asm volatile(
        "mma.sync.aligned.m16n8k32.row.col.s32.s8.s8.s32 "
        "{%0,%1,%2,%3},{%4,%5,%6,%7},{%8,%9},{%0,%1,%2,%3};"
        : "+r"(d[0]), "+r"(d[1]), "+r"(d[2]), "+r"(d[3])
        : "r"(a[0]), "r"(a[1]), "r"(a[2]), "r"(a[3]), "r"(b[0]), "r"(b[1]));
}
#define CP_ASYNC16(dst, src) \
    asm volatile("cp.async.cg.shared.global [%0], [%1], 16;\n" ::"r"(dst), "l"(src))

// C[m,n] = sum_k A[m,k]*B[n,k]; A:[M,K] s8, B:[N,K] s8. Tile 128x128, BK=64 B.
// MODE 1: A=g_xq, B=g_w1q -> StarReLU -> g_h.  MODE 2: A=g_hq, B=g_w2q -> Cout.
template <int K, int MODE>
__global__ void __launch_bounds__(256) gemm_q(float* __restrict__ Cout,
                                              const float* __restrict__ act_s,
                                              const float* __restrict__ act_b) {
    constexpr int BM = 128, BN = 128, BK = 64, PKB = 80;  // 80B pitch: conflict-free
    constexpr int KT = K / BK;
    const int8_t* __restrict__ A = (MODE == 1) ? g_xq : g_hq;
    const int8_t* __restrict__ B = (MODE == 1) ? g_w1q : g_w2q;
    const float* __restrict__ rsc = (MODE == 1) ? g_xs : g_hs;
    const int N = (MODE == 1) ? HID : DIM;
    float* __restrict__ C = (MODE == 1) ? g_h : Cout;

    __shared__ int8_t sA[2][BM * PKB];   // 2 x 10240 B
    __shared__ int8_t sB[2][BN * PKB];   // 2 x 10240 B

    const int tid = threadIdx.x;
    // loaders: 512 16B-chunks per tile per matrix -> 2 chunks/thread each
    const int r0 = tid >> 1;                 // chunk row for first pair (c = tid)
    // chunk c -> row = c>>2, cc = c&3 (4 x 16B chunks per 64B row)
    const uint32_t sAb = (uint32_t)__cvta_generic_to_shared(&sA[0][0]);
    const uint32_t sBb = (uint32_t)__cvta_generic_to_shared(&sB[0][0]);

    auto load_tile = [&](int kt, int st) {
        const int koff = kt * BK;
        const uint32_t so = st * BM * PKB;
#pragma unroll
        for (int i = 0; i < 2; i++) {
            int c = tid + i * 256, row = c >> 2, cc = c & 3;
            CP_ASYNC16(sAb + so + row * PKB + cc * 16,
                       A + ((size_t)blockIdx.y * BM + row) * K + koff + cc * 16);
            CP_ASYNC16(sBb + so + row * PKB + cc * 16,
                       B + ((size_t)blockIdx.x * BN + row) * K + koff + cc * 16);
        }
        asm volatile("cp.async.commit_group;\n" ::);
    };
    (void)r0;

    const int lane = tid & 31, w = tid >> 5;
    const int wm = (w & 1) * 64;       // 2 warps over M
    const int wn = (w >> 1) * 32;      // 4 warps over N
    const int g = lane >> 2, tg = lane & 3;

    int32_t acc[4][4][4];
#pragma unroll
    for (int mt = 0; mt < 4; mt++)
#pragma unroll
        for (int nt = 0; nt < 4; nt++)
#pragma unroll
            for (int r = 0; r < 4; r++) acc[mt][nt][r] = 0;

    load_tile(0, 0);

    for (int kt = 0; kt < KT; ++kt) {
        if (kt + 1 < KT) {
            load_tile(kt + 1, (kt + 1) & 1);
            asm volatile("cp.async.wait_group 1;\n" ::: "memory");
        } else {
            asm volatile("cp.async.wait_group 0;\n" ::: "memory");
        }
        __syncthreads();

        const int8_t* a_s = sA[kt & 1];
        const int8_t* b_s = sB[kt & 1];
#pragma unroll
        for (int ks = 0; ks < 2; ks++) {     // two k32 steps per 64B row
            uint32_t af[4][4], bfr[4][2];
#pragma unroll
            for (int mt = 0; mt < 4; mt++) {
                const int8_t* p = a_s + (wm + mt * 16 + g) * PKB + ks * 32 + tg * 4;
                af[mt][0] = *(const uint32_t*)p;
                af[mt][2] = *(const uint32_t*)(p + 16);
                const int8_t* p8 = p + 8 * PKB;
                af[mt][1] = *(const uint32_t*)p8;
                af[mt][3] = *(const uint32_t*)(p8 + 16);
            }
#pragma unroll
            for (int nt = 0; nt < 4; nt++) {
                const int8_t* p = b_s + (wn + nt * 8 + g) * PKB + ks * 32 + tg * 4;
                bfr[nt][0] = *(const uint32_t*)p;
                bfr[nt][1] = *(const uint32_t*)(p + 16);
            }
#pragma unroll
            for (int mt = 0; mt < 4; mt++)
#pragma unroll
                for (int nt = 0; nt < 4; nt++) imma16832(acc[mt][nt], af[mt], bfr[nt]);
        }
        __syncthreads();
    }

    // epilogue
    const float rw = g_scales[(MODE == 1) ? 1 : 3];
    float vs = 0.f, vb = 0.f;
    if (MODE == 1) { vs = *act_s; vb = *act_b; }

#pragma unroll
    for (int mt = 0; mt < 4; mt++) {
        const int m = blockIdx.y * BM + wm + mt * 16 + g;
        const float f0 = rsc[m] * rw;
        const float f1 = rsc[m + 8] * rw;
#pragma unroll
        for (int nt = 0; nt < 4; nt++) {
            const int n = blockIdx.x * BN + wn + nt * 8 + tg * 2;
            float v0 = (float)acc[mt][nt][0] * f0;
            float v1 = (float)acc[mt][nt][1] * f0;
            float v2 = (float)acc[mt][nt][2] * f1;
            float v3 = (float)acc[mt][nt][3] * f1;
            if (MODE == 1) {
                float a0 = fmaxf(v0, 0.f), a1 = fmaxf(v1, 0.f);
                float a2 = fmaxf(v2, 0.f), a3 = fmaxf(v3, 0.f);
                v0 = vs * a0 * a0 + vb; v1 = vs * a1 * a1 + vb;
                v2 = vs * a2 * a2 + vb; v3 = vs * a3 * a3 + vb;
            }
            *(float2*)&C[(size_t)m * N + n]       = make_float2(v0, v1);
            *(float2*)&C[(size_t)(m + 8) * N + n] = make_float2(v2, v3);
        }
    }
}

// ------------------------- launch ------------------------------------------
extern "C" void kernel_launch(void* const* d_in, const int* in_sizes, int n_in,
                              void* d_out, int out_size) {
    const float* x    = (const float*)d_in[0];   // [4,2048,1024]
    const float* nw1  = (const float*)d_in[1];   // [1024]
    const float* w1   = (const float*)d_in[2];   // [4096,1024]
    const float* as_p = (const float*)d_in[3];   // [1]
    const float* ab_p = (const float*)d_in[4];   // [1]
    const float* nw2  = (const float*)d_in[5];   // [4096]
    const float* w2   = (const float*)d_in[6];   // [1024,4096]
    float* out = (float*)d_out;

    absmean_part<<<1024, 256>>>(w1, 0);
    absmean_part<<<1024, 256>>>(w2, 1);
    finalize_scales<<<1, 256>>>();
    weight_quant_k<<<WNEL / 1024, 256>>>(w1, 0);
    weight_quant_k<<<WNEL / 1024, 256>>>(w2, 1);

    act_quant<DIM, 0><<<MTOK, 256>>>(x, nw1);
    gemm_q<DIM, 1><<<dim3(HID / 128, MTOK / 128), 256>>>(nullptr, as_p, ab_p);
    act_quant<HID, 1><<<MTOK, 256>>>(nullptr, nw2);
    gemm_q<HID, 2><<<dim3(DIM / 128, MTOK / 128), 256>>>(out, nullptr, nullptr);
}

// round 8
// speedup vs baseline: 1.8531x; 1.8531x over previous
#include <cuda_runtime.h>
#include <cuda_bf16.h>
#include <cstdint>

// ---------------------------------------------------------------------------
// BitNet-style MLP via exact-integer bf16 tensor-core GEMMs (legacy mma.sync).
//   activation codes q in [-128,127] and ternary weights t in {-1,0,1} are
//   exact in bf16; fp32 accumulation of |acc| <= 1024*127 < 2^24 is exact.
// tcgen05 unavailable (harness ptxas target sm_103 rejects it); int8 IMMA
// measured 4x slower per-inst than HMMA on this chip. So: bf16 HMMA with
// ldmatrix fragments and 64x64 warp tiles.
// ---------------------------------------------------------------------------

constexpr int MTOK = 8192;
constexpr int DIM  = 1024;
constexpr int HID  = 4096;
constexpr int WNEL = HID * DIM;

// ------------------------- device scratch ----------------------------------
__device__ __align__(16) __nv_bfloat16 g_xq[MTOK * DIM];
__device__ __align__(16) __nv_bfloat16 g_hq[(size_t)MTOK * HID];
__device__ __align__(16) __nv_bfloat16 g_w1q[WNEL];
__device__ __align__(16) __nv_bfloat16 g_w2q[WNEL];
__device__ __align__(16) float         g_h[(size_t)MTOK * HID];
__device__ float g_xs[MTOK];
__device__ float g_hs[MTOK];
__device__ float g_part[2][1024];
__device__ float g_scales[4];   // s1, 1/s1, s2, 1/s2

// ------------------------- reductions --------------------------------------
__device__ __forceinline__ float warpSum(float v) {
#pragma unroll
    for (int o = 16; o > 0; o >>= 1) v += __shfl_xor_sync(0xffffffffu, v, o);
    return v;
}
__device__ __forceinline__ float warpMax(float v) {
#pragma unroll
    for (int o = 16; o > 0; o >>= 1) v = fmaxf(v, __shfl_xor_sync(0xffffffffu, v, o));
    return v;
}
__device__ float blockSum(float v) {
    __shared__ float sh[8];
    v = warpSum(v);
    if ((threadIdx.x & 31) == 0) sh[threadIdx.x >> 5] = v;
    __syncthreads();
    if (threadIdx.x == 0) {
        float t = sh[0];
#pragma unroll
        for (int i = 1; i < 8; i++) t += sh[i];
        sh[0] = t;
    }
    __syncthreads();
    float r = sh[0];
    __syncthreads();
    return r;
}
__device__ float blockMax(float v) {
    __shared__ float sh[8];
    v = warpMax(v);
    if ((threadIdx.x & 31) == 0) sh[threadIdx.x >> 5] = v;
    __syncthreads();
    if (threadIdx.x == 0) {
        float t = sh[0];
#pragma unroll
        for (int i = 1; i < 8; i++) t = fmaxf(t, sh[i]);
        sh[0] = t;
    }
    __syncthreads();
    float r = sh[0];
    __syncthreads();
    return r;
}

// ------------------------- weight quantization ------------------------------
__global__ void absmean_part(const float* __restrict__ w, int which) {
    float s = 0.f;
    for (int i = blockIdx.x * 256 + threadIdx.x; i < WNEL; i += 1024 * 256)
        s += fabsf(w[i]);
    s = blockSum(s);
    if (threadIdx.x == 0) g_part[which][blockIdx.x] = s;
}
__global__ void finalize_scales() {
    float s1 = 0.f, s2 = 0.f;
    for (int i = threadIdx.x; i < 1024; i += 256) { s1 += g_part[0][i]; s2 += g_part[1][i]; }
    s1 = blockSum(s1);
    s2 = blockSum(s2);
    if (threadIdx.x == 0) {
        float sc1 = __fdiv_rn(1.f, fmaxf(__fdiv_rn(s1, (float)WNEL), 1e-5f));
        float sc2 = __fdiv_rn(1.f, fmaxf(__fdiv_rn(s2, (float)WNEL), 1e-5f));
        g_scales[0] = sc1; g_scales[1] = __fdiv_rn(1.f, sc1);
        g_scales[2] = sc2; g_scales[3] = __fdiv_rn(1.f, sc2);
    }
}
__global__ void weight_quant_k(const float* __restrict__ w, int which) {
    __nv_bfloat16* __restrict__ wq = which ? g_w2q : g_w1q;
    float s = g_scales[which * 2];
    size_t i = ((size_t)blockIdx.x * 256 + threadIdx.x) * 4;
    float4 v = *(const float4*)(w + i);
    float t0 = fminf(fmaxf(rintf(v.x * s), -1.f), 1.f);
    float t1 = fminf(fmaxf(rintf(v.y * s), -1.f), 1.f);
    float t2 = fminf(fmaxf(rintf(v.z * s), -1.f), 1.f);
    float t3 = fminf(fmaxf(rintf(v.w * s), -1.f), 1.f);
    __nv_bfloat162 p0 = __nv_bfloat162(__float2bfloat16_rn(t0), __float2bfloat16_rn(t1));
    __nv_bfloat162 p1 = __nv_bfloat162(__float2bfloat16_rn(t2), __float2bfloat16_rn(t3));
    uint2 pk;
    pk.x = *(const unsigned int*)&p0;
    pk.y = *(const unsigned int*)&p1;
    *(uint2*)(wq + i) = pk;
}

// ------------------------- rmsnorm + activation quant -----------------------
template <int D, int STAGE>
__global__ void act_quant(const float* __restrict__ xin, const float* __restrict__ nw) {
    constexpr int E = D / 1024;
    const float* __restrict__ in = (STAGE == 0) ? xin : g_h;
    __nv_bfloat16* __restrict__ xq = (STAGE == 0) ? g_xq : g_hq;
    float* __restrict__ xs = (STAGE == 0) ? g_xs : g_hs;
    size_t base = (size_t)blockIdx.x * D;

    float4 v[E], wv[E];
    float ss = 0.f;
#pragma unroll
    for (int e = 0; e < E; e++) {
        int idx = (e * 256 + threadIdx.x) * 4;
        v[e]  = *(const float4*)(in + base + idx);
        wv[e] = *(const float4*)(nw + idx);
        ss += v[e].x * v[e].x + v[e].y * v[e].y + v[e].z * v[e].z + v[e].w * v[e].w;
    }
    ss = blockSum(ss);
    float rsq = __fdiv_rn(1.f, __fsqrt_rn(__fdiv_rn(ss, (float)D) + 1e-8f));

    float mx = 0.f;
#pragma unroll
    for (int e = 0; e < E; e++) {
        v[e].x *= rsq * wv[e].x; v[e].y *= rsq * wv[e].y;
        v[e].z *= rsq * wv[e].z; v[e].w *= rsq * wv[e].w;
        mx = fmaxf(mx, fmaxf(fmaxf(fabsf(v[e].x), fabsf(v[e].y)),
                             fmaxf(fabsf(v[e].z), fabsf(v[e].w))));
    }
    mx = blockMax(mx);
    float sc = __fdiv_rn(127.f, fmaxf(mx, 1e-5f));

#pragma unroll
    for (int e = 0; e < E; e++) {
        int idx = (e * 256 + threadIdx.x) * 4;
        float q0 = fminf(fmaxf(rintf(v[e].x * sc), -128.f), 127.f);
        float q1 = fminf(fmaxf(rintf(v[e].y * sc), -128.f), 127.f);
        float q2 = fminf(fmaxf(rintf(v[e].z * sc), -128.f), 127.f);
        float q3 = fminf(fmaxf(rintf(v[e].w * sc), -128.f), 127.f);
        __nv_bfloat162 p0 = __nv_bfloat162(__float2bfloat16_rn(q0), __float2bfloat16_rn(q1));
        __nv_bfloat162 p1 = __nv_bfloat162(__float2bfloat16_rn(q2), __float2bfloat16_rn(q3));
        uint2 pk;
        pk.x = *(const unsigned int*)&p0;
        pk.y = *(const unsigned int*)&p1;
        *(uint2*)(xq + base + idx) = pk;
    }
    if (threadIdx.x == 0) xs[blockIdx.x] = __fdiv_rn(1.f, sc);
}

// ------------------------- GEMM --------------------------------------------
__device__ __forceinline__ void mma16816(float* d, const uint32_t* a, const uint32_t* b) {
    asm volatile(
        "mma.sync.aligned.m16n8k16.row.col.f32.bf16.bf16.f32 "
        "{%0,%1,%2,%3},{%4,%5,%6,%7},{%8,%9},{%0,%1,%2,%3};"
        : "+f"(d[0]), "+f"(d[1]), "+f"(d[2]), "+f"(d[3])
        : "r"(a[0]), "r"(a[1]), "r"(a[2]), "r"(a[3]), "r"(b[0]), "r"(b[1]));
}
#define CP_ASYNC16(dst, src) \
    asm volatile("cp.async.cg.shared.global [%0], [%1], 16;\n" ::"r"(dst), "l"(src))
#define LDSM_X4(r0, r1, r2, r3, addr)                                          \
    asm volatile("ldmatrix.sync.aligned.m8n8.x4.shared.b16 {%0,%1,%2,%3}, [%4];" \
                 : "=r"(r0), "=r"(r1), "=r"(r2), "=r"(r3) : "r"(addr))

// C[m,n] = sum_k A[m,k]*B[n,k]; bf16 codes. Tile BM=128 x BN=256, BK=32.
// 8 warps as 2(M) x 4(N); warp tile 64x64. Fragments via ldmatrix.x4.
// MODE 1: A=g_xq, B=g_w1q -> StarReLU -> g_h.  MODE 2: A=g_hq, B=g_w2q -> Cout.
template <int K, int MODE>
__global__ void __launch_bounds__(256) gemm_q(float* __restrict__ Cout,
                                              const float* __restrict__ act_s,
                                              const float* __restrict__ act_b) {
    constexpr int BM = 128, BN = 256, BK = 32;
    constexpr int PKB = 80;                   // smem pitch bytes (40 bf16)
    constexpr int KT = K / BK;
    constexpr int A_STAGE = BM * PKB;         // 10240 B
    constexpr int B_STAGE = BN * PKB;         // 20480 B
    const __nv_bfloat16* __restrict__ A = (MODE == 1) ? g_xq : g_hq;
    const __nv_bfloat16* __restrict__ B = (MODE == 1) ? g_w1q : g_w2q;
    const float* __restrict__ rsc = (MODE == 1) ? g_xs : g_hs;
    const int N = (MODE == 1) ? HID : DIM;
    float* __restrict__ C = (MODE == 1) ? g_h : Cout;

    extern __shared__ char dsm[];
    const uint32_t sAb = (uint32_t)__cvta_generic_to_shared(dsm);
    const uint32_t sBb = sAb + 2 * A_STAGE;

    const int tid = threadIdx.x;
    const int lane = tid & 31, w = tid >> 5;
    const int wm = (w & 1) * 64;        // 2 warps over M (64 rows each)
    const int wn = (w >> 1) * 64;       // 4 warps over N (64 cols each)
    const int g = lane >> 2, tg = lane & 3;

    // cp.async loader: A = 512 16B chunks, B = 1024 chunks; 6 per thread
    auto load_tile = [&](int kt, int st) {
        const int koff = kt * BK;
        const uint32_t sa = sAb + st * A_STAGE, sb = sBb + st * B_STAGE;
#pragma unroll
        for (int i = 0; i < 2; i++) {       // A: rows 0..127, 4 chunks/row
            int c = tid + i * 256, row = c >> 2, cc = c & 3;
            CP_ASYNC16(sa + row * PKB + cc * 16,
                       A + ((size_t)blockIdx.y * BM + row) * K + koff + cc * 8);
        }
#pragma unroll
        for (int i = 0; i < 4; i++) {       // B: rows 0..255, 4 chunks/row
            int c = tid + i * 256, row = c >> 2, cc = c & 3;
            CP_ASYNC16(sb + row * PKB + cc * 16,
                       B + ((size_t)blockIdx.x * BN + row) * K + koff + cc * 8);
        }
        asm volatile("cp.async.commit_group;\n" ::);
    };

    // ldmatrix per-lane address bases (byte offsets within a stage)
    // A (x4 -> a0..a3 = [m0-7,k0][m8-15,k0][m0-7,k8][m8-15,k8]):
    const uint32_t aLane = (uint32_t)((wm + (lane & 15)) * PKB + (lane >> 4) * 16);
    // B (x4 over an nt pair -> [n0-7,k0][n0-7,k8][n8-15,k0][n8-15,k8]):
    const uint32_t bLane = (uint32_t)((wn + (lane & 7) + (lane >> 4) * 8) * PKB +
                                      ((lane >> 3) & 1) * 16);

    float acc[4][8][4];
#pragma unroll
    for (int mt = 0; mt < 4; mt++)
#pragma unroll
        for (int nt = 0; nt < 8; nt++)
#pragma unroll
            for (int r = 0; r < 4; r++) acc[mt][nt][r] = 0.f;

    load_tile(0, 0);

    for (int kt = 0; kt < KT; ++kt) {
        if (kt + 1 < KT) {
            load_tile(kt + 1, (kt + 1) & 1);
            asm volatile("cp.async.wait_group 1;\n" ::: "memory");
        } else {
            asm volatile("cp.async.wait_group 0;\n" ::: "memory");
        }
        __syncthreads();

        const uint32_t sa = sAb + (kt & 1) * A_STAGE;
        const uint32_t sb = sBb + (kt & 1) * B_STAGE;
#pragma unroll
        for (int ks = 0; ks < 2; ks++) {          // two k16 steps per BK=32
            const uint32_t ko = ks * 32;          // 16 bf16 = 32 bytes
            uint32_t af[4][4], bfr[8][2];
#pragma unroll
            for (int mt = 0; mt < 4; mt++)
                LDSM_X4(af[mt][0], af[mt][1], af[mt][2], af[mt][3],
                        sa + aLane + mt * (16 * PKB) + ko);
#pragma unroll
            for (int np = 0; np < 4; np++)        // nt pairs (2np, 2np+1)
                LDSM_X4(bfr[2 * np][0], bfr[2 * np][1],
                        bfr[2 * np + 1][0], bfr[2 * np + 1][1],
                        sb + bLane + np * (16 * PKB) + ko);
#pragma unroll
            for (int mt = 0; mt < 4; mt++)
#pragma unroll
                for (int nt = 0; nt < 8; nt++) mma16816(acc[mt][nt], af[mt], bfr[nt]);
        }
        __syncthreads();
    }

    // epilogue
    const float rw = g_scales[(MODE == 1) ? 1 : 3];
    float vs = 0.f, vb = 0.f;
    if (MODE == 1) { vs = *act_s; vb = *act_b; }

#pragma unroll
    for (int mt = 0; mt < 4; mt++) {
        const int m = blockIdx.y * BM + wm + mt * 16 + g;
        const float f0 = rsc[m] * rw;
        const float f1 = rsc[m + 8] * rw;
#pragma unroll
        for (int nt = 0; nt < 8; nt++) {
            const int n = blockIdx.x * BN + wn + nt * 8 + tg * 2;
            float v0 = acc[mt][nt][0] * f0;
            float v1 = acc[mt][nt][1] * f0;
            float v2 = acc[mt][nt][2] * f1;
            float v3 = acc[mt][nt][3] * f1;
            if (MODE == 1) {
                float a0 = fmaxf(v0, 0.f), a1 = fmaxf(v1, 0.f);
                float a2 = fmaxf(v2, 0.f), a3 = fmaxf(v3, 0.f);
                v0 = vs * a0 * a0 + vb; v1 = vs * a1 * a1 + vb;
                v2 = vs * a2 * a2 + vb; v3 = vs * a3 * a3 + vb;
            }
            *(float2*)&C[(size_t)m * N + n]       = make_float2(v0, v1);
            *(float2*)&C[(size_t)(m + 8) * N + n] = make_float2(v2, v3);
        }
    }
}

// ------------------------- launch ------------------------------------------
extern "C" void kernel_launch(void* const* d_in, const int* in_sizes, int n_in,
                              void* d_out, int out_size) {
    const float* x    = (const float*)d_in[0];   // [4,2048,1024]
    const float* nw1  = (const float*)d_in[1];   // [1024]
    const float* w1   = (const float*)d_in[2];   // [4096,1024]
    const float* as_p = (const float*)d_in[3];   // [1]
    const float* ab_p = (const float*)d_in[4];   // [1]
    const float* nw2  = (const float*)d_in[5];   // [4096]
    const float* w2   = (const float*)d_in[6];   // [1024,4096]
    float* out = (float*)d_out;

    constexpr int SMEM = 2 * 10240 + 2 * 20480;  // 61440 B
    cudaFuncSetAttribute(gemm_q<DIM, 1>, cudaFuncAttributeMaxDynamicSharedMemorySize, SMEM);
    cudaFuncSetAttribute(gemm_q<HID, 2>, cudaFuncAttributeMaxDynamicSharedMemorySize, SMEM);

    absmean_part<<<1024, 256>>>(w1, 0);
    absmean_part<<<1024, 256>>>(w2, 1);
    finalize_scales<<<1, 256>>>();
    weight_quant_k<<<WNEL / 1024, 256>>>(w1, 0);
    weight_quant_k<<<WNEL / 1024, 256>>>(w2, 1);

    act_quant<DIM, 0><<<MTOK, 256>>>(x, nw1);
    gemm_q<DIM, 1><<<dim3(HID / 256, MTOK / 128), 256, SMEM>>>(nullptr, as_p, ab_p);
    act_quant<HID, 1><<<MTOK, 256>>>(nullptr, nw2);
    gemm_q<HID, 2><<<dim3(DIM / 256, MTOK / 128), 256, SMEM>>>(out, nullptr, nullptr);
}